// round 5
// baseline (speedup 1.0000x reference)
#include <cuda_runtime.h>

// ---------------------------------------------------------------------------
// NeuralODE Tsit5 — persistent fused kernel, v5 "K-split".
// CTA = 16 batch rows, 512 threads (16 warps, 4/SMSP). All weights in SMEM.
// Two warp-groups split K in half; each warp covers 16 rows x 16 cols so
// every weight byte crosses the SMEM crossbar exactly once per stage.
// Group B writes partial sums to SMEM; group A merges + bias + ReLU.
// f32x2 packed FMA (FFMA2) over K, horizontal add at the end.
// ---------------------------------------------------------------------------

#define NTHREADS 512
#define M_TILE   16

__constant__ float d_cs[6] = {0.0f, 0.161f, 0.327f, 0.9f, 0.9800255409045097f, 1.0f};
__constant__ float d_A[6][5] = {
    {0.f, 0.f, 0.f, 0.f, 0.f},
    {0.161f, 0.f, 0.f, 0.f, 0.f},
    {-0.008480655492356989f, 0.335480655492357f, 0.f, 0.f, 0.f},
    {2.8971530571054935f, -6.359448489975075f, 4.3622954328695815f, 0.f, 0.f},
    {5.325864828439257f, -11.748883564062828f, 7.4955393428898365f, -0.09249506636175525f, 0.f},
    {5.86145544294642f, -12.92096931784711f, 8.159367898576159f, -0.071584973281401f, -0.028269050394068383f}
};
__constant__ float d_B[6] = {
    0.09646076681806523f, 0.01f, 0.4798896504144996f,
    1.379008574103742f, -3.290069515436081f, 2.324710524099774f
};

// ---- f32x2 helpers ---------------------------------------------------------
__device__ __forceinline__ unsigned long long pack2(float x, float y) {
    unsigned long long r;
    asm("mov.b64 %0, {%1, %2};" : "=l"(r) : "f"(x), "f"(y));
    return r;
}
__device__ __forceinline__ float2 unpack2(unsigned long long v) {
    float2 f;
    asm("mov.b64 {%0, %1}, %2;" : "=f"(f.x), "=f"(f.y) : "l"(v));
    return f;
}
__device__ __forceinline__ void ffma2(unsigned long long& d,
                                      unsigned long long a,
                                      unsigned long long b) {
    asm("fma.rn.f32x2 %0, %1, %2, %0;" : "+l"(d) : "l"(a), "l"(b));
}

// ---- sizes / strides (floats) ----------------------------------------------
// Act row strides s satisfy s*4 mod 128 in {16,48,80,112} so the 8 lane-row
// groups hit 8 distinct 16-B sectors (conflict-free LDS.128), 16-B aligned.
#define KP0 36      // layer0 k-pairs: 72 floats = t + 64 y + 7 zero-pad
#define KP1 64
#define KP2W 64
#define SA0 76      // 304 B  % 128 = 48
#define SA1 132     // 528 B  % 128 = 16
#define SKB 68      // 272 B  % 128 = 16
#define PB  132     // partial buffer stride
#define KBROW (M_TILE*SKB)

#define U64_WORDS (KP0*128 + KP1*128 + KP2W*64)
#define F32_WORDS (128 + 128 + 64 + M_TILE*SA0 + 2*M_TILE*SA1 + 6*KBROW + M_TILE*64 + M_TILE*PB)
#define SMEM_BYTES (U64_WORDS*8 + F32_WORDS*4)

// ---- half-K MLP layer ------------------------------------------------------
// All 512 threads call this. actG/wpG are pre-offset to the group's k-start.
// Warp tile: 16 rows x (N/8) cols; lane (lr=lane>>2, lc=lane&3) owns rows
// {lr, lr+8} and CT = N/32 cols at ct. Group B stores partials; A merges.
template<int N, int KP2H, int SIN, int SOUT, bool RELU>
__device__ __forceinline__ void mlp_layer(const float* __restrict__ actG,
                                          const unsigned long long* __restrict__ wpG,
                                          const float* __restrict__ bias,
                                          float* __restrict__ pbuf,
                                          float* __restrict__ actOut,
                                          bool ga, int lr, int ct) {
    constexpr int CT = N / 32;               // 4 (N=128) or 2 (N=64)
    const float* a0p = actG + lr * SIN;
    const float* a1p = a0p + 8 * SIN;
    const unsigned long long* wb = wpG + ct;

    unsigned long long acc0[CT], acc1[CT];
#pragma unroll
    for (int c = 0; c < CT; c++) { acc0[c] = 0ull; acc1[c] = 0ull; }

#pragma unroll 4
    for (int kp2 = 0; kp2 < KP2H; kp2++) {
        ulonglong2 a0 = *reinterpret_cast<const ulonglong2*>(a0p + 4 * kp2);
        ulonglong2 a1 = *reinterpret_cast<const ulonglong2*>(a1p + 4 * kp2);
        const unsigned long long* wr0 = wb + (2 * kp2) * N;
        const unsigned long long* wr1 = wr0 + N;
#pragma unroll
        for (int j2 = 0; j2 < CT / 2; j2++) {
            ulonglong2 wA = *reinterpret_cast<const ulonglong2*>(wr0 + 2 * j2);
            ulonglong2 wB = *reinterpret_cast<const ulonglong2*>(wr1 + 2 * j2);
            ffma2(acc0[2*j2],   a0.x, wA.x);
            ffma2(acc0[2*j2+1], a0.x, wA.y);
            ffma2(acc1[2*j2],   a1.x, wA.x);
            ffma2(acc1[2*j2+1], a1.x, wA.y);
            ffma2(acc0[2*j2],   a0.y, wB.x);
            ffma2(acc0[2*j2+1], a0.y, wB.y);
            ffma2(acc1[2*j2],   a1.y, wB.x);
            ffma2(acc1[2*j2+1], a1.y, wB.y);
        }
    }

    // horizontal add
    float s0[CT], s1[CT];
#pragma unroll
    for (int c = 0; c < CT; c++) {
        float2 p0 = unpack2(acc0[c]); s0[c] = p0.x + p0.y;
        float2 p1 = unpack2(acc1[c]); s1[c] = p1.x + p1.y;
    }

    if (!ga) {  // group B: park partials
        if constexpr (CT == 4) {
            *reinterpret_cast<float4*>(pbuf + lr * PB + ct) =
                make_float4(s0[0], s0[1], s0[2], s0[3]);
            *reinterpret_cast<float4*>(pbuf + (lr + 8) * PB + ct) =
                make_float4(s1[0], s1[1], s1[2], s1[3]);
        } else {
            *reinterpret_cast<float2*>(pbuf + lr * PB + ct) = make_float2(s0[0], s0[1]);
            *reinterpret_cast<float2*>(pbuf + (lr + 8) * PB + ct) = make_float2(s1[0], s1[1]);
        }
    }
    __syncthreads();
    if (ga) {   // group A: merge + bias (+ReLU) + store
        float q0[CT], q1[CT];
        if constexpr (CT == 4) {
            float4 t0 = *reinterpret_cast<const float4*>(pbuf + lr * PB + ct);
            float4 t1 = *reinterpret_cast<const float4*>(pbuf + (lr + 8) * PB + ct);
            q0[0]=t0.x; q0[1]=t0.y; q0[2]=t0.z; q0[3]=t0.w;
            q1[0]=t1.x; q1[1]=t1.y; q1[2]=t1.z; q1[3]=t1.w;
        } else {
            float2 t0 = *reinterpret_cast<const float2*>(pbuf + lr * PB + ct);
            float2 t1 = *reinterpret_cast<const float2*>(pbuf + (lr + 8) * PB + ct);
            q0[0]=t0.x; q0[1]=t0.y; q1[0]=t1.x; q1[1]=t1.y;
        }
        float v0[CT], v1[CT];
#pragma unroll
        for (int c = 0; c < CT; c++) {
            float bv = bias[ct + c];
            v0[c] = s0[c] + q0[c] + bv;
            v1[c] = s1[c] + q1[c] + bv;
            if (RELU) { v0[c] = fmaxf(v0[c], 0.f); v1[c] = fmaxf(v1[c], 0.f); }
        }
        float* o0 = actOut + lr * SOUT + ct;
        float* o1 = actOut + (lr + 8) * SOUT + ct;
        if constexpr (CT == 4) {
            *reinterpret_cast<float4*>(o0) = make_float4(v0[0], v0[1], v0[2], v0[3]);
            *reinterpret_cast<float4*>(o1) = make_float4(v1[0], v1[1], v1[2], v1[3]);
        } else {
            *reinterpret_cast<float2*>(o0) = make_float2(v0[0], v0[1]);
            *reinterpret_cast<float2*>(o1) = make_float2(v1[0], v1[1]);
        }
    }
}

// ---------------------------------------------------------------------------
__global__ void __launch_bounds__(NTHREADS, 1)
node_kernel(const float* __restrict__ y0, const float* __restrict__ ts,
            const float* __restrict__ w0, const float* __restrict__ b0,
            const float* __restrict__ w1, const float* __restrict__ b1,
            const float* __restrict__ w2, const float* __restrict__ b2,
            float* __restrict__ out, int T) {
    extern __shared__ unsigned long long smem_u64[];
    unsigned long long* wp0 = smem_u64;
    unsigned long long* wp1 = wp0 + KP0 * 128;
    unsigned long long* wp2 = wp1 + KP1 * 128;
    float* fb   = reinterpret_cast<float*>(wp2 + KP2W * 64);
    float* sb0  = fb;            fb += 128;
    float* sb1  = fb;            fb += 128;
    float* sb2  = fb;            fb += 64;
    float* act0 = fb;            fb += M_TILE * SA0;
    float* act1 = fb;            fb += M_TILE * SA1;
    float* act2 = fb;            fb += M_TILE * SA1;
    float* kbuf = fb;            fb += 6 * KBROW;
    float* ysh  = fb;            fb += M_TILE * 64;
    float* pbuf = fb;

    const int tid  = threadIdx.x;
    const int lane = tid & 31;
    const int warp = tid >> 5;
    const bool ga  = (warp < 8);             // group A: warps 0-7
    const int wg   = warp & 7;               // warp index within group
    const int lr   = lane >> 2;              // lane-row 0..7 -> rows {lr, lr+8}
    const int lc   = lane & 3;
    const int row0 = blockIdx.x * M_TILE;

    const int ct128 = wg * 16 + lc * 4;      // N=128: 4 cols per lane
    const int ct64  = wg * 8  + lc * 2;      // N=64:  2 cols per lane

    // group-adjusted base pointers (K-split halves)
    const float* act0G = act0 + (ga ? 0 : 36);
    const float* act1G = act1 + (ga ? 0 : 64);
    const float* act2G = act2 + (ga ? 0 : 64);
    const unsigned long long* wp0G = wp0 + (ga ? 0 : 18 * 128);
    const unsigned long long* wp1G = wp1 + (ga ? 0 : 32 * 128);
    const unsigned long long* wp2G = wp2 + (ga ? 0 : 32 * 64);

    // ---- one-time setup: packed transposed weights, biases, y, act0 pad ----
    for (int idx = tid; idx < KP0 * 128; idx += NTHREADS) {
        int kp = idx >> 7, n = idx & 127;
        int k0 = 2 * kp, k1 = 2 * kp + 1;
        float a = (k0 < 65) ? w0[n * 65 + k0] : 0.0f;
        float b = (k1 < 65) ? w0[n * 65 + k1] : 0.0f;
        wp0[idx] = pack2(a, b);
    }
    for (int idx = tid; idx < KP1 * 128; idx += NTHREADS) {
        int kp = idx >> 7, n = idx & 127;
        wp1[idx] = pack2(w1[n * 128 + 2 * kp], w1[n * 128 + 2 * kp + 1]);
    }
    for (int idx = tid; idx < KP2W * 64; idx += NTHREADS) {
        int kp = idx >> 6, n = idx & 63;
        wp2[idx] = pack2(w2[n * 128 + 2 * kp], w2[n * 128 + 2 * kp + 1]);
    }
    for (int idx = tid; idx < 128; idx += NTHREADS) { sb0[idx] = b0[idx]; sb1[idx] = b1[idx]; }
    for (int idx = tid; idx < 64;  idx += NTHREADS) sb2[idx] = b2[idx];
    for (int idx = tid; idx < M_TILE * 64; idx += NTHREADS)
        ysh[idx] = y0[row0 * 64 + idx];
    if (tid < M_TILE) {                       // zero act0 K-pad cols 65..71
#pragma unroll
        for (int kk = 65; kk < 72; kk++) act0[tid * SA0 + kk] = 0.0f;
    }
    __syncthreads();

    const float dt = ts[1] - ts[0];
    const int steps = T - 1;

    // prologue/epilogue mapping: thread covers 2 consecutive cols of one row
    const int pr = tid >> 5;            // row 0..15
    const int pc = (tid & 31) * 2;      // col 0..62

    for (int st = 0; st < steps; st++) {
        const float t = ts[st];
        for (int s = 0; s < 6; s++) {
            // ---- prologue: act0 = [t_s, y + dt * sum_j A[s][j] k_j, pad] ----
            if (pc == 0) act0[pr * SA0] = fmaf(d_cs[s], dt, t);
#pragma unroll
            for (int q = 0; q < 2; q++) {
                float acc = 0.0f;
                for (int j = 0; j < s; j++)
                    acc = fmaf(d_A[s][j], kbuf[j * KBROW + pr * SKB + pc + q], acc);
                act0[pr * SA0 + 1 + pc + q] = fmaf(dt, acc, ysh[pr * 64 + pc + q]);
            }
            __syncthreads();
            mlp_layer<128,  9, SA0, SA1, true >(act0G, wp0G, sb0, pbuf, act1, ga, lr, ct128);
            __syncthreads();
            mlp_layer<128, 16, SA1, SA1, true >(act1G, wp1G, sb1, pbuf, act2, ga, lr, ct128);
            __syncthreads();
            mlp_layer<64,  16, SA1, SKB, false>(act2G, wp2G, sb2, pbuf,
                                                kbuf + s * KBROW, ga, lr, ct64);
            __syncthreads();
        }
        // ---- y += dt * sum_j B[j] k_j ----
#pragma unroll
        for (int q = 0; q < 2; q++) {
            const int kc = pr * SKB + pc + q;
            float acc = d_B[0] * kbuf[kc];
#pragma unroll
            for (int j = 1; j < 6; j++)
                acc = fmaf(d_B[j], kbuf[j * KBROW + kc], acc);
            ysh[pr * 64 + pc + q] = fmaf(dt, acc, ysh[pr * 64 + pc + q]);
        }
        __syncthreads();
    }

    for (int idx = tid; idx < M_TILE * 64; idx += NTHREADS)
        out[row0 * 64 + idx] = ysh[idx];
}

// ---------------------------------------------------------------------------
extern "C" void kernel_launch(void* const* d_in, const int* in_sizes, int n_in,
                              void* d_out, int out_size) {
    const float* y0 = (const float*)d_in[0];
    const float* ts = (const float*)d_in[1];
    const float* w0 = (const float*)d_in[2];
    const float* b0 = (const float*)d_in[3];
    const float* w1 = (const float*)d_in[4];
    const float* b1 = (const float*)d_in[5];
    const float* w2 = (const float*)d_in[6];
    const float* b2 = (const float*)d_in[7];

    const int B = in_sizes[0] / 64;   // batch rows
    const int T = in_sizes[1];        // number of time points

    cudaFuncSetAttribute(node_kernel,
                         cudaFuncAttributeMaxDynamicSharedMemorySize, SMEM_BYTES);

    node_kernel<<<B / M_TILE, NTHREADS, SMEM_BYTES>>>(
        y0, ts, w0, b0, w1, b1, w2, b2, (float*)d_out, T);
}

// round 6
// speedup vs baseline: 1.1210x; 1.1210x over previous
#include <cuda_runtime.h>

// ---------------------------------------------------------------------------
// NeuralODE Tsit5 — persistent fused kernel, v6 "fat register tiles".
// CTA = 16 batch rows, 128 threads (4 warps). All weights in SMEM.
// Each warp covers the FULL 16x128 output tile with lane tile 8 rows x 8 cols
// (128 acc regs) and K split 4 ways across warps; partial sums reduced via
// SMEM. Phase-model-optimal: ~2 bytes requested per f32x2 FMA.
// ---------------------------------------------------------------------------

#define NTHREADS 128
#define M_TILE   16

__constant__ float d_cs[6] = {0.0f, 0.161f, 0.327f, 0.9f, 0.9800255409045097f, 1.0f};
__constant__ float d_A[6][5] = {
    {0.f, 0.f, 0.f, 0.f, 0.f},
    {0.161f, 0.f, 0.f, 0.f, 0.f},
    {-0.008480655492356989f, 0.335480655492357f, 0.f, 0.f, 0.f},
    {2.8971530571054935f, -6.359448489975075f, 4.3622954328695815f, 0.f, 0.f},
    {5.325864828439257f, -11.748883564062828f, 7.4955393428898365f, -0.09249506636175525f, 0.f},
    {5.86145544294642f, -12.92096931784711f, 8.159367898576159f, -0.071584973281401f, -0.028269050394068383f}
};
__constant__ float d_B[6] = {
    0.09646076681806523f, 0.01f, 0.4798896504144996f,
    1.379008574103742f, -3.290069515436081f, 2.324710524099774f
};

// ---- f32x2 helpers ---------------------------------------------------------
__device__ __forceinline__ unsigned long long pack2(float x, float y) {
    unsigned long long r;
    asm("mov.b64 %0, {%1, %2};" : "=l"(r) : "f"(x), "f"(y));
    return r;
}
__device__ __forceinline__ float2 unpack2(unsigned long long v) {
    float2 f;
    asm("mov.b64 {%0, %1}, %2;" : "=f"(f.x), "=f"(f.y) : "l"(v));
    return f;
}
__device__ __forceinline__ void ffma2(unsigned long long& d,
                                      unsigned long long a,
                                      unsigned long long b) {
    asm("fma.rn.f32x2 %0, %1, %2, %0;" : "+l"(d) : "l"(a), "l"(b));
}

// ---- sizes / strides (floats) ----------------------------------------------
#define KP0 36      // layer0 k-pairs: 72 = t + 64 y + 7 zero pad
#define KP1 64
#define KP2 64
#define KPW0 9      // k-pairs per warp (K split 4 ways)
#define KPW1 16
#define KPW2 16
#define SA0 72
#define SA1 132
#define SKB 68
#define PB  130     // partial-buffer row stride: 8*PB % 32 == 16 -> the two
                    // row-groups hit disjoint bank halves (conflict-free STS.32)
#define PBSLOT (M_TILE*PB)
#define KBROW  (M_TILE*SKB)

#define U64_WORDS (KP0*128 + KP1*128 + KP2*64)
#define F32_WORDS (128 + 128 + 64 + M_TILE*SA0 + 2*M_TILE*SA1 + 6*KBROW + M_TILE*64 + 4*PBSLOT)
#define SMEM_BYTES (U64_WORDS*8 + F32_WORDS*4)   // ~216 KB

// ---- streaming GEMM slice + partial store ----------------------------------
// Warp covers 16 rows x N cols, its K-quarter. Lane (rowg=lane>>4, colg=lane&15)
// owns rows rowg*8..+7 and cols {colg + 16*j, j<CT}. Partial f32 sums go to
// pb (pre-offset to this warp's slot + rowg*8*PB + colg).
template<int N, int CT, int KPW, int SIN>
__device__ __forceinline__ void stream_store(const float* __restrict__ arow,
                                             const unsigned long long* __restrict__ wk,
                                             float* __restrict__ pb) {
    unsigned long long acc[8][CT];
#pragma unroll
    for (int i = 0; i < 8; i++)
#pragma unroll
        for (int j = 0; j < CT; j++) acc[i][j] = 0ull;

#pragma unroll 2
    for (int kp = 0; kp < KPW; kp++) {
        unsigned long long a[8];
#pragma unroll
        for (int i = 0; i < 8; i++)
            a[i] = *reinterpret_cast<const unsigned long long*>(arow + i * SIN + 2 * kp);
        const unsigned long long* wr = wk + kp * N;
#pragma unroll
        for (int j = 0; j < CT; j++) {
            unsigned long long w = wr[16 * j];
#pragma unroll
            for (int i = 0; i < 8; i++) ffma2(acc[i][j], a[i], w);
        }
    }
    // horizontal add, store f32 partials (STS.32, conflict-free by PB choice)
#pragma unroll
    for (int i = 0; i < 8; i++)
#pragma unroll
        for (int j = 0; j < CT; j++) {
            float2 p = unpack2(acc[i][j]);
            pb[i * PB + 16 * j] = p.x + p.y;
        }
}

// ---- reduce 4 partial buffers -> dst[16 x N] (+bias, optional ReLU) --------
// Warp w handles cols [w*NQ, (w+1)*NQ); lane: row rr=lane>>1, col half ch.
template<int NQ, int SOUT, bool RELU>
__device__ __forceinline__ void reduce_store(const float* __restrict__ pbuf,
                                             const float* __restrict__ bias,
                                             float* __restrict__ dst,
                                             int warp, int lane) {
    constexpr int M2 = NQ / 4;               // float2 chunks per lane
    const int rr = lane >> 1;
    const int c0 = warp * NQ + (lane & 1) * (NQ / 2);

    float2 v[M2];
#pragma unroll
    for (int m = 0; m < M2; m++)
        v[m] = *reinterpret_cast<const float2*>(bias + c0 + 2 * m);
#pragma unroll
    for (int b = 0; b < 4; b++) {
        const float* p = pbuf + b * PBSLOT + rr * PB + c0;
#pragma unroll
        for (int m = 0; m < M2; m++) {
            float2 t = *reinterpret_cast<const float2*>(p + 2 * m);
            v[m].x += t.x; v[m].y += t.y;
        }
    }
    float* o = dst + rr * SOUT + c0;
#pragma unroll
    for (int m = 0; m < M2; m++) {
        float x = v[m].x, y = v[m].y;
        if (RELU) { x = fmaxf(x, 0.f); y = fmaxf(y, 0.f); }
        *reinterpret_cast<float2*>(o + 2 * m) = make_float2(x, y);
    }
}

// ---------------------------------------------------------------------------
__global__ void __launch_bounds__(NTHREADS, 1)
node_kernel(const float* __restrict__ y0, const float* __restrict__ ts,
            const float* __restrict__ w0, const float* __restrict__ b0,
            const float* __restrict__ w1, const float* __restrict__ b1,
            const float* __restrict__ w2, const float* __restrict__ b2,
            float* __restrict__ out, int T) {
    extern __shared__ unsigned long long smem_u64[];
    unsigned long long* wp0 = smem_u64;
    unsigned long long* wp1 = wp0 + KP0 * 128;
    unsigned long long* wp2 = wp1 + KP1 * 128;
    float* fb   = reinterpret_cast<float*>(wp2 + KP2 * 64);
    float* sb0  = fb;            fb += 128;
    float* sb1  = fb;            fb += 128;
    float* sb2  = fb;            fb += 64;
    float* act0 = fb;            fb += M_TILE * SA0;
    float* act1 = fb;            fb += M_TILE * SA1;
    float* act2 = fb;            fb += M_TILE * SA1;
    float* kbuf = fb;            fb += 6 * KBROW;
    float* ysh  = fb;            fb += M_TILE * 64;
    float* pbuf = fb;

    const int tid  = threadIdx.x;
    const int lane = tid & 31;
    const int warp = tid >> 5;               // 0..3 = K quarter
    const int rowg = lane >> 4;              // 0..1 -> rows rowg*8..+7
    const int colg = lane & 15;              // cols colg + 16*j
    const int row0 = blockIdx.x * M_TILE;

    // ---- one-time setup: packed transposed weights, biases, y, act0 pad ----
    for (int idx = tid; idx < KP0 * 128; idx += NTHREADS) {
        int kp = idx >> 7, n = idx & 127;
        int k0 = 2 * kp, k1 = 2 * kp + 1;
        float a = (k0 < 65) ? w0[n * 65 + k0] : 0.0f;
        float b = (k1 < 65) ? w0[n * 65 + k1] : 0.0f;
        wp0[idx] = pack2(a, b);
    }
    for (int idx = tid; idx < KP1 * 128; idx += NTHREADS) {
        int kp = idx >> 7, n = idx & 127;
        wp1[idx] = pack2(w1[n * 128 + 2 * kp], w1[n * 128 + 2 * kp + 1]);
    }
    for (int idx = tid; idx < KP2 * 64; idx += NTHREADS) {
        int kp = idx >> 6, n = idx & 63;
        wp2[idx] = pack2(w2[n * 128 + 2 * kp], w2[n * 128 + 2 * kp + 1]);
    }
    for (int idx = tid; idx < 128; idx += NTHREADS) { sb0[idx] = b0[idx]; sb1[idx] = b1[idx]; }
    for (int idx = tid; idx < 64;  idx += NTHREADS) sb2[idx] = b2[idx];
    for (int idx = tid; idx < M_TILE * 64; idx += NTHREADS)
        ysh[idx] = y0[row0 * 64 + idx];
    if (tid < M_TILE) {                      // zero act0 K-pad cols 65..71
#pragma unroll
        for (int kk = 65; kk < 72; kk++) act0[tid * SA0 + kk] = 0.0f;
    }
    __syncthreads();

    const float dt = ts[1] - ts[0];
    const int steps = T - 1;

    // warp-fixed pointers (K-quarter offsets)
    float* pbW = pbuf + warp * PBSLOT + rowg * 8 * PB + colg;
    const unsigned long long* wk0 = wp0 + (warp * KPW0) * 128 + colg;
    const unsigned long long* wk1 = wp1 + (warp * KPW1) * 128 + colg;
    const unsigned long long* wk2 = wp2 + (warp * KPW2) * 64 + colg;
    const int aoff0 = rowg * 8 * SA0 + 2 * (warp * KPW0);
    const int aoff1 = rowg * 8 * SA1 + 2 * (warp * KPW1);

    // prologue/epilogue mapping: thread = row pr, 8 consecutive cols at pc
    const int pr = tid >> 3;
    const int pc = (tid & 7) * 8;

    for (int st = 0; st < steps; st++) {
        const float t = ts[st];
        for (int s = 0; s < 6; s++) {
            // ---- prologue: act0 = [t_s, y + dt * sum_j A[s][j] k_j, pad] ----
            if ((tid & 7) == 0) act0[pr * SA0] = fmaf(d_cs[s], dt, t);
#pragma unroll
            for (int q = 0; q < 8; q++) {
                float acc = 0.0f;
                for (int j = 0; j < s; j++)
                    acc = fmaf(d_A[s][j], kbuf[j * KBROW + pr * SKB + pc + q], acc);
                act0[pr * SA0 + 1 + pc + q] = fmaf(dt, acc, ysh[pr * 64 + pc + q]);
            }
            __syncthreads();

            stream_store<128, 8, KPW0, SA0>(act0 + aoff0, wk0, pbW);
            __syncthreads();
            reduce_store<32, SA1, true>(pbuf, sb0, act1, warp, lane);
            __syncthreads();

            stream_store<128, 8, KPW1, SA1>(act1 + aoff1, wk1, pbW);
            __syncthreads();
            reduce_store<32, SA1, true>(pbuf, sb1, act2, warp, lane);
            __syncthreads();

            stream_store<64, 4, KPW2, SA1>(act2 + aoff1, wk2, pbW);
            __syncthreads();
            reduce_store<16, SKB, false>(pbuf, sb2, kbuf + s * KBROW, warp, lane);
            __syncthreads();
        }
        // ---- y += dt * sum_j B[j] k_j ----
#pragma unroll
        for (int q = 0; q < 8; q++) {
            const int kc = pr * SKB + pc + q;
            float acc = d_B[0] * kbuf[kc];
#pragma unroll
            for (int j = 1; j < 6; j++)
                acc = fmaf(d_B[j], kbuf[j * KBROW + kc], acc);
            ysh[pr * 64 + pc + q] = fmaf(dt, acc, ysh[pr * 64 + pc + q]);
        }
        __syncthreads();
    }

    for (int idx = tid; idx < M_TILE * 64; idx += NTHREADS)
        out[row0 * 64 + idx] = ysh[idx];
}

// ---------------------------------------------------------------------------
extern "C" void kernel_launch(void* const* d_in, const int* in_sizes, int n_in,
                              void* d_out, int out_size) {
    const float* y0 = (const float*)d_in[0];
    const float* ts = (const float*)d_in[1];
    const float* w0 = (const float*)d_in[2];
    const float* b0 = (const float*)d_in[3];
    const float* w1 = (const float*)d_in[4];
    const float* b1 = (const float*)d_in[5];
    const float* w2 = (const float*)d_in[6];
    const float* b2 = (const float*)d_in[7];

    const int B = in_sizes[0] / 64;   // batch rows
    const int T = in_sizes[1];        // number of time points

    cudaFuncSetAttribute(node_kernel,
                         cudaFuncAttributeMaxDynamicSharedMemorySize, SMEM_BYTES);

    node_kernel<<<B / M_TILE, NTHREADS, SMEM_BYTES>>>(
        y0, ts, w0, b0, w1, b1, w2, b2, (float*)d_out, T);
}

// round 7
// speedup vs baseline: 1.1423x; 1.0190x over previous
#include <cuda_runtime.h>

// ---------------------------------------------------------------------------
// NeuralODE Tsit5 — persistent fused kernel, v7.
// CTA = 16 batch rows, 256 threads (8 warps, 2/SMSP). All weights in SMEM.
// Warp = (K-quarter, row-half): covers 8 rows x N cols of its K quarter with
// lane tile 4 rows x 8 cols (64 u64 accumulators). 4 partial-sum slots in
// SMEM (one per K quarter), reduced by all 8 warps. f32x2 packed FMA.
// ---------------------------------------------------------------------------

#define NTHREADS 256
#define M_TILE   16

__constant__ float d_cs[6] = {0.0f, 0.161f, 0.327f, 0.9f, 0.9800255409045097f, 1.0f};
__constant__ float d_A[6][5] = {
    {0.f, 0.f, 0.f, 0.f, 0.f},
    {0.161f, 0.f, 0.f, 0.f, 0.f},
    {-0.008480655492356989f, 0.335480655492357f, 0.f, 0.f, 0.f},
    {2.8971530571054935f, -6.359448489975075f, 4.3622954328695815f, 0.f, 0.f},
    {5.325864828439257f, -11.748883564062828f, 7.4955393428898365f, -0.09249506636175525f, 0.f},
    {5.86145544294642f, -12.92096931784711f, 8.159367898576159f, -0.071584973281401f, -0.028269050394068383f}
};
__constant__ float d_B[6] = {
    0.09646076681806523f, 0.01f, 0.4798896504144996f,
    1.379008574103742f, -3.290069515436081f, 2.324710524099774f
};

// ---- f32x2 helpers ---------------------------------------------------------
__device__ __forceinline__ unsigned long long pack2(float x, float y) {
    unsigned long long r;
    asm("mov.b64 %0, {%1, %2};" : "=l"(r) : "f"(x), "f"(y));
    return r;
}
__device__ __forceinline__ float2 unpack2(unsigned long long v) {
    float2 f;
    asm("mov.b64 {%0, %1}, %2;" : "=f"(f.x), "=f"(f.y) : "l"(v));
    return f;
}
__device__ __forceinline__ void ffma2(unsigned long long& d,
                                      unsigned long long a,
                                      unsigned long long b) {
    asm("fma.rn.f32x2 %0, %1, %2, %0;" : "+l"(d) : "l"(a), "l"(b));
}

// ---- sizes / strides (floats) ----------------------------------------------
#define KP0 40      // layer0 k-pairs: 80 = t + 64 y + 15 zero pad (4x10 split)
#define KP1 64
#define KP2 64
#define KPW0 10     // k-pairs per warp (K split 4 ways)
#define KPW1 16
#define KPW2 16
#define SA0 84      // 84*4 % 16 == 0 (LDS.128 ok); 4 rows apart -> +16 banks
#define SA1 132
#define SKB 68
#define PB  132     // 4*PB % 32 == 16 -> the two 4-row lane groups hit
                    // disjoint bank halves on STS/LDS
#define PBSLOT (M_TILE*PB)
#define KBROW  (M_TILE*SKB)

#define U64_WORDS (KP0*128 + KP1*128 + KP2*64)
#define F32_WORDS (128 + 128 + 64 + M_TILE*SA0 + 2*M_TILE*SA1 + 6*KBROW + M_TILE*64 + 4*PBSLOT)
#define SMEM_BYTES (U64_WORDS*8 + F32_WORDS*4)   // ~227 KB

// ---- streaming GEMM slice + partial store ----------------------------------
// Warp covers 8 rows (its row half) x N cols, its K quarter.
// Lane (rowg=lane>>4, colg=lane&15): rows rowbase + rowg*4 + i (i<4),
// cols colg + 16*j (j<CT). arow/wk/pb pre-offset per warp+lane.
template<int N, int CT, int KPW, int SIN>
__device__ __forceinline__ void stream_store(const float* __restrict__ arow,
                                             const unsigned long long* __restrict__ wk,
                                             float* __restrict__ pb) {
    unsigned long long acc[4][CT];
#pragma unroll
    for (int i = 0; i < 4; i++)
#pragma unroll
        for (int j = 0; j < CT; j++) acc[i][j] = 0ull;

#pragma unroll 2
    for (int kp2 = 0; kp2 < KPW / 2; kp2++) {
        ulonglong2 a[4];
#pragma unroll
        for (int i = 0; i < 4; i++)
            a[i] = *reinterpret_cast<const ulonglong2*>(arow + i * SIN + 4 * kp2);
        const unsigned long long* wr0 = wk + (2 * kp2) * N;
        const unsigned long long* wr1 = wr0 + N;
#pragma unroll
        for (int j = 0; j < CT; j++) {
            unsigned long long w0 = wr0[16 * j];
            unsigned long long w1 = wr1[16 * j];
#pragma unroll
            for (int i = 0; i < 4; i++) {
                ffma2(acc[i][j], a[i].x, w0);
                ffma2(acc[i][j], a[i].y, w1);
            }
        }
    }
    // horizontal add + store f32 partials (conflict-free by PB choice)
#pragma unroll
    for (int i = 0; i < 4; i++)
#pragma unroll
        for (int j = 0; j < CT; j++) {
            float2 p = unpack2(acc[i][j]);
            pb[i * PB + 16 * j] = p.x + p.y;
        }
}

// ---- reduce 4 partial slots -> dst[16 x N] (+bias, optional ReLU) ----------
// Warp w handles cols [w*NQ, (w+1)*NQ); lane: row rr=lane>>1, half lane&1.
template<int NQ, int SOUT, bool RELU>
__device__ __forceinline__ void reduce_store(const float* __restrict__ pbuf,
                                             const float* __restrict__ bias,
                                             float* __restrict__ dst,
                                             int warp, int lane) {
    constexpr int M2 = NQ / 4;               // float2 chunks per lane
    const int rr = lane >> 1;
    const int c0 = warp * NQ + (lane & 1) * (NQ / 2);

    float2 v[M2];
#pragma unroll
    for (int m = 0; m < M2; m++)
        v[m] = *reinterpret_cast<const float2*>(bias + c0 + 2 * m);
#pragma unroll
    for (int b = 0; b < 4; b++) {
        const float* p = pbuf + b * PBSLOT + rr * PB + c0;
#pragma unroll
        for (int m = 0; m < M2; m++) {
            float2 t = *reinterpret_cast<const float2*>(p + 2 * m);
            v[m].x += t.x; v[m].y += t.y;
        }
    }
    float* o = dst + rr * SOUT + c0;
#pragma unroll
    for (int m = 0; m < M2; m++) {
        float x = v[m].x, y = v[m].y;
        if (RELU) { x = fmaxf(x, 0.f); y = fmaxf(y, 0.f); }
        *reinterpret_cast<float2*>(o + 2 * m) = make_float2(x, y);
    }
}

// ---------------------------------------------------------------------------
__global__ void __launch_bounds__(NTHREADS, 1)
node_kernel(const float* __restrict__ y0, const float* __restrict__ ts,
            const float* __restrict__ w0, const float* __restrict__ b0,
            const float* __restrict__ w1, const float* __restrict__ b1,
            const float* __restrict__ w2, const float* __restrict__ b2,
            float* __restrict__ out, int T) {
    extern __shared__ unsigned long long smem_u64[];
    unsigned long long* wp0 = smem_u64;
    unsigned long long* wp1 = wp0 + KP0 * 128;
    unsigned long long* wp2 = wp1 + KP1 * 128;
    float* fb   = reinterpret_cast<float*>(wp2 + KP2 * 64);
    float* sb0  = fb;            fb += 128;
    float* sb1  = fb;            fb += 128;
    float* sb2  = fb;            fb += 64;
    float* act0 = fb;            fb += M_TILE * SA0;
    float* act1 = fb;            fb += M_TILE * SA1;
    float* act2 = fb;            fb += M_TILE * SA1;
    float* kbuf = fb;            fb += 6 * KBROW;
    float* ysh  = fb;            fb += M_TILE * 64;
    float* pbuf = fb;

    const int tid  = threadIdx.x;
    const int lane = tid & 31;
    const int warp = tid >> 5;
    const int q    = warp >> 1;              // K quarter 0..3
    const int h    = warp & 1;               // row half 0..1
    const int rowg = lane >> 4;              // 0..1 -> 4-row subgroup
    const int colg = lane & 15;              // cols colg + 16*j
    const int row0 = blockIdx.x * M_TILE;
    const int rowbase = h * 8 + rowg * 4;    // first of this lane's 4 rows

    // ---- one-time setup: packed transposed weights, biases, y, act0 pad ----
    for (int idx = tid; idx < KP0 * 128; idx += NTHREADS) {
        int kp = idx >> 7, n = idx & 127;
        int k0 = 2 * kp, k1 = 2 * kp + 1;
        float a = (k0 < 65) ? w0[n * 65 + k0] : 0.0f;
        float b = (k1 < 65) ? w0[n * 65 + k1] : 0.0f;
        wp0[idx] = pack2(a, b);
    }
    for (int idx = tid; idx < KP1 * 128; idx += NTHREADS) {
        int kp = idx >> 7, n = idx & 127;
        wp1[idx] = pack2(w1[n * 128 + 2 * kp], w1[n * 128 + 2 * kp + 1]);
    }
    for (int idx = tid; idx < KP2 * 64; idx += NTHREADS) {
        int kp = idx >> 6, n = idx & 63;
        wp2[idx] = pack2(w2[n * 128 + 2 * kp], w2[n * 128 + 2 * kp + 1]);
    }
    for (int idx = tid; idx < 128; idx += NTHREADS) { sb0[idx] = b0[idx]; sb1[idx] = b1[idx]; }
    for (int idx = tid; idx < 64;  idx += NTHREADS) sb2[idx] = b2[idx];
    for (int idx = tid; idx < M_TILE * 64; idx += NTHREADS)
        ysh[idx] = y0[row0 * 64 + idx];
    if (tid < M_TILE) {                      // zero act0 K-pad cols 65..79
#pragma unroll
        for (int kk = 65; kk < 80; kk++) act0[tid * SA0 + kk] = 0.0f;
    }
    __syncthreads();

    const float dt = ts[1] - ts[0];
    const int steps = T - 1;

    // warp/lane-fixed pointers (K-quarter offsets)
    float* pbW = pbuf + q * PBSLOT + rowbase * PB + colg;
    const unsigned long long* wk0 = wp0 + (q * KPW0) * 128 + colg;
    const unsigned long long* wk1 = wp1 + (q * KPW1) * 128 + colg;
    const unsigned long long* wk2 = wp2 + (q * KPW2) * 64 + colg;
    const float* a0W = act0 + rowbase * SA0 + 2 * (q * KPW0);
    const float* a1W = act1 + rowbase * SA1 + 2 * (q * KPW1);
    const float* a2W = act2 + rowbase * SA1 + 2 * (q * KPW2);

    // prologue/epilogue mapping: thread = row pr, 4 consecutive cols at pc
    const int pr = tid >> 4;
    const int pc = (tid & 15) * 4;

    for (int st = 0; st < steps; st++) {
        const float t = ts[st];
        for (int s = 0; s < 6; s++) {
            // ---- prologue: act0 = [t_s, y + dt * sum_j A[s][j] k_j, pad] ----
            if (pc == 0) act0[pr * SA0] = fmaf(d_cs[s], dt, t);
#pragma unroll
            for (int qq = 0; qq < 4; qq++) {
                float acc = 0.0f;
                for (int j = 0; j < s; j++)
                    acc = fmaf(d_A[s][j], kbuf[j * KBROW + pr * SKB + pc + qq], acc);
                act0[pr * SA0 + 1 + pc + qq] = fmaf(dt, acc, ysh[pr * 64 + pc + qq]);
            }
            __syncthreads();

            stream_store<128, 8, KPW0, SA0>(a0W, wk0, pbW);
            __syncthreads();
            reduce_store<16, SA1, true>(pbuf, sb0, act1, warp, lane);
            __syncthreads();

            stream_store<128, 8, KPW1, SA1>(a1W, wk1, pbW);
            __syncthreads();
            reduce_store<16, SA1, true>(pbuf, sb1, act2, warp, lane);
            __syncthreads();

            stream_store<64, 4, KPW2, SA1>(a2W, wk2, pbW);
            __syncthreads();
            reduce_store<8, SKB, false>(pbuf, sb2, kbuf + s * KBROW, warp, lane);
            __syncthreads();
        }
        // ---- y += dt * sum_j B[j] k_j ----
#pragma unroll
        for (int qq = 0; qq < 4; qq++) {
            const int kc = pr * SKB + pc + qq;
            float acc = d_B[0] * kbuf[kc];
#pragma unroll
            for (int j = 1; j < 6; j++)
                acc = fmaf(d_B[j], kbuf[j * KBROW + kc], acc);
            ysh[pr * 64 + pc + qq] = fmaf(dt, acc, ysh[pr * 64 + pc + qq]);
        }
        __syncthreads();
    }

    for (int idx = tid; idx < M_TILE * 64; idx += NTHREADS)
        out[row0 * 64 + idx] = ysh[idx];
}

// ---------------------------------------------------------------------------
extern "C" void kernel_launch(void* const* d_in, const int* in_sizes, int n_in,
                              void* d_out, int out_size) {
    const float* y0 = (const float*)d_in[0];
    const float* ts = (const float*)d_in[1];
    const float* w0 = (const float*)d_in[2];
    const float* b0 = (const float*)d_in[3];
    const float* w1 = (const float*)d_in[4];
    const float* b1 = (const float*)d_in[5];
    const float* w2 = (const float*)d_in[6];
    const float* b2 = (const float*)d_in[7];

    const int B = in_sizes[0] / 64;   // batch rows
    const int T = in_sizes[1];        // number of time points

    cudaFuncSetAttribute(node_kernel,
                         cudaFuncAttributeMaxDynamicSharedMemorySize, SMEM_BYTES);

    node_kernel<<<B / M_TILE, NTHREADS, SMEM_BYTES>>>(
        y0, ts, w0, b0, w1, b1, w2, b2, (float*)d_out, T);
}